// round 13
// baseline (speedup 1.0000x reference)
#include <cuda_runtime.h>
#include <cuda_bf16.h>

#define IMG_W 1024
#define IMG_H 1024
#define KS 15
#define NB 32

// Input tile staged in smem: x covers [bx*256-8, bx*256+264) = 272 floats,
// y covers [by*32-7, by*32+39) = 46 rows. Zero-padded outside the image.
// sShift is the same tile shifted by one float (sShift[x] = sIn[x+1]) so
// odd-offset f32 pairs are naturally aligned for LDS.128 / FFMA2.
#define TILE_W 272
#define TILE_HH 46
#define TILE_ELEMS (TILE_W * TILE_HH)
#define SIN_OFF   512
#define SSH_OFF   (SIN_OFF + (TILE_ELEMS + 4) * 4)
#define SMEM_BYTES (SSH_OFF + (TILE_ELEMS + 4) * 4)

typedef unsigned long long u64;

// ---- packed fp32x2 helpers (Blackwell, PTX-only) ----
__device__ __forceinline__ u64 pack2(float lo, float hi) {
    u64 r;
    asm("mov.b64 %0, {%1, %2};" : "=l"(r) : "f"(lo), "f"(hi));
    return r;
}
__device__ __forceinline__ void unpack2(u64 v, float& lo, float& hi) {
    asm("mov.b64 {%0, %1}, %2;" : "=f"(lo), "=f"(hi) : "l"(v));
}
__device__ __forceinline__ void fma2(u64& d, u64 a, u64 b) {
    asm("fma.rn.f32x2 %0, %1, %2, %3;" : "=l"(d) : "l"(a), "l"(b), "l"(d));
}
__device__ __forceinline__ u64 add2(u64 a, u64 b) {
    u64 r;
    asm("add.rn.f32x2 %0, %1, %2;" : "=l"(r) : "l"(a), "l"(b));
    return r;
}
__device__ __forceinline__ unsigned smem_u32(const void* p) {
    unsigned r;
    asm("{ .reg .u64 t; cvta.to.shared.u64 t, %1; cvt.u32.u64 %0, t; }" : "=r"(r) : "l"(p));
    return r;
}

// Thread: 4 px (two f32x2 pairs) x 8 output rows. Block 256 thr = 8 warps:
// 2 in x, 4 in y. Block tile: 256 px * 32 rows. Grid (4, 32, 32).
// Weights (dx+dy folded Airy symmetry): 8 rows x 8 (w,w) pairs in smem;
// each weight fetch serves BOTH dy-symmetric output rows.
__global__ __launch_bounds__(256, 2) void stem_conv_roll(
    const float* __restrict__ in, const float* __restrict__ kern,
    const int* __restrict__ shifts, float* __restrict__ out)
{
    extern __shared__ char dynsmem[];
    u64*   sk     = reinterpret_cast<u64*>(dynsmem);            // 512B
    float* sIn    = reinterpret_cast<float*>(dynsmem + SIN_OFF);
    float* sShift = reinterpret_cast<float*>(dynsmem + SSH_OFF);

    const int tid = threadIdx.x;
    const int b   = blockIdx.z;
    const float* img = in + (size_t)b * (IMG_H * IMG_W);

    // ---- Stage input tile via cp.async, zero-filled outside the image.
    // Every partially-OOB float4 in this geometry is fully OOB, so
    // src_size=0 zfill handles all padding.
    {
        const int gxb = blockIdx.x * 256 - 8;
        const int gyb = blockIdx.y * 32 - 7;
        const unsigned sbase = smem_u32(dynsmem) + SIN_OFF;
        for (int idx = tid; idx < TILE_HH * (TILE_W / 4); idx += 256) {
            const int ry  = idx / (TILE_W / 4);
            const int rx4 = idx - ry * (TILE_W / 4);
            const int gy  = gyb + ry;
            const int gx  = gxb + rx4 * 4;
            const bool ok = (gy >= 0) && (gy < IMG_H) && (gx >= 0) && (gx <= IMG_W - 4);
            const float* src = ok ? (img + (size_t)gy * IMG_W + gx) : img;
            const unsigned dst = sbase + (unsigned)(ry * TILE_W + rx4 * 4) * 4u;
            const int sz = ok ? 16 : 0;
            asm volatile("cp.async.ca.shared.global [%0], [%1], 16, %2;"
                         :: "r"(dst), "l"(src), "r"(sz));
        }
    }

    // Folded weights (overlaps staging): sk[wr*8+e] = (w,w), w = k[wr][7+e].
    if (tid < 64) {
        int wr = tid >> 3, e = tid & 7;
        float w = kern[wr * KS + 7 + e];
        sk[tid] = pack2(w, w);
    }
    asm volatile("cp.async.commit_group;\n\tcp.async.wait_group 0;" ::: "memory");
    __syncthreads();

    // ---- Build shifted copy: sShift[i] = sIn[i+1] (per row it's the row
    // shifted left by one float; the cross-row seam values are never read).
    for (int idx = tid; idx < TILE_ELEMS / 4; idx += 256) {
        const int base = idx * 4;
        float4 a = *reinterpret_cast<const float4*>(sIn + base);
        float  c = sIn[base + 4];   // pad slot makes the last read safe
        *reinterpret_cast<float4*>(sShift + base) = make_float4(a.y, a.z, a.w, c);
    }
    __syncthreads();

    const int lane = tid & 31;
    const int warp = tid >> 5;
    const int wx = warp & 1;
    const int wy = warp >> 1;
    const int xl = wx * 128 + lane * 4;       // local x of first px (mult of 4)
    const int x0 = blockIdx.x * 256 + xl;
    const int y0 = blockIdx.y * 32 + wy * 8;

    u64 acc0[8], acc1[8];
    #pragma unroll
    for (int r = 0; r < 8; ++r) { acc0[r] = 0ull; acc1[r] = 0ull; }

    const float* tbase = sIn    + wy * 8 * TILE_W + xl;
    const float* sbase = sShift + wy * 8 * TILE_W + xl;

    #pragma unroll
    for (int g = 0; g < 22; ++g) {
        // Aligned pairs s_j = (ga[2j], ga[2j+1]) from sIn,
        // odd pairs    t_j = (ga[2j+1], ga[2j+2]) from sShift — all LDS.128.
        const ulonglong2* tr2 = reinterpret_cast<const ulonglong2*>(tbase + g * TILE_W);
        const ulonglong2* sh2 = reinterpret_cast<const ulonglong2*>(sbase + g * TILE_W);
        ulonglong2 p0 = tr2[0], p1 = tr2[1], p2 = tr2[2], p3 = tr2[3], p4 = tr2[4];
        ulonglong2 q0 = sh2[0], q1 = sh2[1], q2 = sh2[2], q3 = sh2[3], q4 = sh2[4];
        u64 s1 = p0.y, s2 = p1.x, s3 = p1.y, s4 = p2.x,
            s5 = p2.y, s6 = p3.x, s7 = p3.y, s8 = p4.x;
        u64 t0 = q0.x, t1 = q0.y, t2 = q1.x, t3 = q1.y, t4 = q2.x,
            t5 = q2.y, t6 = q3.x, t7 = q3.y, t8 = q4.x;

        // Horizontal folds, all packed add2.
        u64 h0[8], h1[8];
        h0[0] = s4;
        h0[1] = add2(t3, t4);
        h0[2] = add2(s3, s5);
        h0[3] = add2(t2, t5);
        h0[4] = add2(s2, s6);
        h0[5] = add2(t1, t6);
        h0[6] = add2(s1, s7);
        h0[7] = add2(t0, t7);

        h1[0] = s5;
        h1[1] = add2(t4, t5);
        h1[2] = add2(s4, s6);
        h1[3] = add2(t3, t6);
        h1[4] = add2(s3, s7);
        h1[5] = add2(t2, t7);
        h1[6] = add2(s2, s8);
        h1[7] = add2(t1, t8);

        // Weight row wr serves BOTH dy-symmetric output rows:
        //   r1 = g - wr (dy = wr), r2 = g - 14 + wr (dy = 14 - wr).
        #pragma unroll
        for (int wr = 0; wr < 8; ++wr) {
            const int r1 = g - wr;
            const int r2 = g - 14 + wr;
            const bool u1 = (r1 >= 0) && (r1 < 8);
            const bool u2 = (wr < 7) && (r2 >= 0) && (r2 < 8);
            if (u1 || u2) {
                const u64* kw = &sk[wr * 8];
                ulonglong2 w01 = *reinterpret_cast<const ulonglong2*>(kw + 0);
                ulonglong2 w23 = *reinterpret_cast<const ulonglong2*>(kw + 2);
                ulonglong2 w45 = *reinterpret_cast<const ulonglong2*>(kw + 4);
                ulonglong2 w67 = *reinterpret_cast<const ulonglong2*>(kw + 6);
                if (u1) {
                    fma2(acc0[r1], h0[0], w01.x);  fma2(acc1[r1], h1[0], w01.x);
                    fma2(acc0[r1], h0[1], w01.y);  fma2(acc1[r1], h1[1], w01.y);
                    fma2(acc0[r1], h0[2], w23.x);  fma2(acc1[r1], h1[2], w23.x);
                    fma2(acc0[r1], h0[3], w23.y);  fma2(acc1[r1], h1[3], w23.y);
                    fma2(acc0[r1], h0[4], w45.x);  fma2(acc1[r1], h1[4], w45.x);
                    fma2(acc0[r1], h0[5], w45.y);  fma2(acc1[r1], h1[5], w45.y);
                    fma2(acc0[r1], h0[6], w67.x);  fma2(acc1[r1], h1[6], w67.x);
                    fma2(acc0[r1], h0[7], w67.y);  fma2(acc1[r1], h1[7], w67.y);
                }
                if (u2) {
                    fma2(acc0[r2], h0[0], w01.x);  fma2(acc1[r2], h1[0], w01.x);
                    fma2(acc0[r2], h0[1], w01.y);  fma2(acc1[r2], h1[1], w01.y);
                    fma2(acc0[r2], h0[2], w23.x);  fma2(acc1[r2], h1[2], w23.x);
                    fma2(acc0[r2], h0[3], w23.y);  fma2(acc1[r2], h1[3], w23.y);
                    fma2(acc0[r2], h0[4], w45.x);  fma2(acc1[r2], h1[4], w45.x);
                    fma2(acc0[r2], h0[5], w45.y);  fma2(acc1[r2], h1[5], w45.y);
                    fma2(acc0[r2], h0[6], w67.x);  fma2(acc1[r2], h1[6], w67.x);
                    fma2(acc0[r2], h0[7], w67.y);  fma2(acc1[r2], h1[7], w67.y);
                }
            }
        }
    }

    // Fused roll: out[b, y, (x + s) & 1023] = conv[b, y, x].
    #pragma unroll
    for (int r = 0; r < 8; ++r) {
        const int y = y0 + r;
        const int s = shifts[b * IMG_H + y];
        float* orow = out + ((size_t)b * IMG_H + y) * IMG_W;
        float lo0, hi0, lo1, hi1;
        unpack2(acc0[r], lo0, hi0);
        unpack2(acc1[r], lo1, hi1);
        int c0 = (x0 + s) & (IMG_W - 1);
        int c1 = (x0 + 2 + s) & (IMG_W - 1);
        if ((s & 1) == 0) {
            // even shift: c0,c1 even -> aligned float2, never straddle the wrap
            *reinterpret_cast<float2*>(orow + c0) = make_float2(lo0, hi0);
            *reinterpret_cast<float2*>(orow + c1) = make_float2(lo1, hi1);
        } else {
            orow[c0] = lo0;
            orow[(c0 + 1) & (IMG_W - 1)] = hi0;
            orow[c1] = lo1;
            orow[(c1 + 1) & (IMG_W - 1)] = hi1;
        }
    }
}

extern "C" void kernel_launch(void* const* d_in, const int* in_sizes, int n_in,
                              void* d_out, int out_size) {
    const float* img = nullptr;
    const float* kern = nullptr;
    const int*   shifts = nullptr;
    for (int i = 0; i < n_in; ++i) {
        if (in_sizes[i] == NB * IMG_H * IMG_W)      img    = (const float*)d_in[i];
        else if (in_sizes[i] == KS * KS)            kern   = (const float*)d_in[i];
        else if (in_sizes[i] == NB * IMG_H)         shifts = (const int*)d_in[i];
    }
    cudaFuncSetAttribute(stem_conv_roll,
                         cudaFuncAttributeMaxDynamicSharedMemorySize, SMEM_BYTES);
    dim3 grid(IMG_W / 256, IMG_H / 32, NB);
    stem_conv_roll<<<grid, 256, SMEM_BYTES>>>(img, kern, shifts, (float*)d_out);
}

// round 14
// speedup vs baseline: 1.0006x; 1.0006x over previous
#include <cuda_runtime.h>
#include <cuda_bf16.h>

#define IMG_W 1024
#define IMG_H 1024
#define KS 15
#define NB 32

// Input tile staged in smem: x covers [bx*256-8, bx*256+264) = 272 floats,
// y covers [by*32-7, by*32+39) = 46 rows. Zero-padded outside the image.
// sShift is the same tile shifted by one float (sShift[x] = sIn[x+1]) so
// odd-offset f32 pairs are naturally aligned for LDS.128 / FFMA2.
#define TILE_W 272
#define TILE_HH 46
#define TILE_ELEMS (TILE_W * TILE_HH)
#define SIN_OFF   512
#define SSH_OFF   (SIN_OFF + (TILE_ELEMS + 4) * 4)
#define SMEM_BYTES (SSH_OFF + (TILE_ELEMS + 4) * 4)

typedef unsigned long long u64;

// ---- packed fp32x2 helpers (Blackwell, PTX-only) ----
__device__ __forceinline__ u64 pack2(float lo, float hi) {
    u64 r;
    asm("mov.b64 %0, {%1, %2};" : "=l"(r) : "f"(lo), "f"(hi));
    return r;
}
__device__ __forceinline__ void unpack2(u64 v, float& lo, float& hi) {
    asm("mov.b64 {%0, %1}, %2;" : "=f"(lo), "=f"(hi) : "l"(v));
}
__device__ __forceinline__ void fma2(u64& d, u64 a, u64 b) {
    asm("fma.rn.f32x2 %0, %1, %2, %3;" : "=l"(d) : "l"(a), "l"(b), "l"(d));
}
__device__ __forceinline__ u64 add2(u64 a, u64 b) {
    u64 r;
    asm("add.rn.f32x2 %0, %1, %2;" : "=l"(r) : "l"(a), "l"(b));
    return r;
}
__device__ __forceinline__ unsigned smem_u32(const void* p) {
    unsigned r;
    asm("{ .reg .u64 t; cvta.to.shared.u64 t, %1; cvt.u32.u64 %0, t; }" : "=r"(r) : "l"(p));
    return r;
}

// Thread: 4 px (two f32x2 pairs) x 8 output rows. Block 256 thr = 8 warps:
// 2 in x, 4 in y. Block tile: 256 px * 32 rows. Grid (4, 32, 32).
// Weights (dx+dy folded Airy symmetry): 8 rows x 8 (w,w) pairs in smem;
// each weight fetch serves BOTH dy-symmetric output rows.
__global__ __launch_bounds__(256, 2) void stem_conv_roll(
    const float* __restrict__ in, const float* __restrict__ kern,
    const int* __restrict__ shifts, float* __restrict__ out)
{
    extern __shared__ char dynsmem[];
    u64*   sk     = reinterpret_cast<u64*>(dynsmem);            // 512B
    float* sIn    = reinterpret_cast<float*>(dynsmem + SIN_OFF);
    float* sShift = reinterpret_cast<float*>(dynsmem + SSH_OFF);

    const int tid = threadIdx.x;
    const int b   = blockIdx.z;
    const float* img = in + (size_t)b * (IMG_H * IMG_W);

    // ---- Stage input tile via cp.async, zero-filled outside the image.
    // Every partially-OOB float4 in this geometry is fully OOB, so
    // src_size=0 zfill handles all padding.
    {
        const int gxb = blockIdx.x * 256 - 8;
        const int gyb = blockIdx.y * 32 - 7;
        const unsigned sbase = smem_u32(dynsmem) + SIN_OFF;
        for (int idx = tid; idx < TILE_HH * (TILE_W / 4); idx += 256) {
            const int ry  = idx / (TILE_W / 4);
            const int rx4 = idx - ry * (TILE_W / 4);
            const int gy  = gyb + ry;
            const int gx  = gxb + rx4 * 4;
            const bool ok = (gy >= 0) && (gy < IMG_H) && (gx >= 0) && (gx <= IMG_W - 4);
            const float* src = ok ? (img + (size_t)gy * IMG_W + gx) : img;
            const unsigned dst = sbase + (unsigned)(ry * TILE_W + rx4 * 4) * 4u;
            const int sz = ok ? 16 : 0;
            asm volatile("cp.async.ca.shared.global [%0], [%1], 16, %2;"
                         :: "r"(dst), "l"(src), "r"(sz));
        }
    }

    // Folded weights (overlaps staging): sk[wr*8+e] = (w,w), w = k[wr][7+e].
    if (tid < 64) {
        int wr = tid >> 3, e = tid & 7;
        float w = kern[wr * KS + 7 + e];
        sk[tid] = pack2(w, w);
    }
    asm volatile("cp.async.commit_group;\n\tcp.async.wait_group 0;" ::: "memory");
    __syncthreads();

    // ---- Build shifted copy: sShift[i] = sIn[i+1] (per row it's the row
    // shifted left by one float; the cross-row seam values are never read).
    for (int idx = tid; idx < TILE_ELEMS / 4; idx += 256) {
        const int base = idx * 4;
        float4 a = *reinterpret_cast<const float4*>(sIn + base);
        float  c = sIn[base + 4];   // pad slot makes the last read safe
        *reinterpret_cast<float4*>(sShift + base) = make_float4(a.y, a.z, a.w, c);
    }
    __syncthreads();

    const int lane = tid & 31;
    const int warp = tid >> 5;
    const int wx = warp & 1;
    const int wy = warp >> 1;
    const int xl = wx * 128 + lane * 4;       // local x of first px (mult of 4)
    const int x0 = blockIdx.x * 256 + xl;
    const int y0 = blockIdx.y * 32 + wy * 8;

    u64 acc0[8], acc1[8];
    #pragma unroll
    for (int r = 0; r < 8; ++r) { acc0[r] = 0ull; acc1[r] = 0ull; }

    const float* tbase = sIn    + wy * 8 * TILE_W + xl;
    const float* sbase = sShift + wy * 8 * TILE_W + xl;

    #pragma unroll
    for (int g = 0; g < 22; ++g) {
        // Aligned pairs s_j = (ga[2j], ga[2j+1]) from sIn,
        // odd pairs    t_j = (ga[2j+1], ga[2j+2]) from sShift — all LDS.128.
        const ulonglong2* tr2 = reinterpret_cast<const ulonglong2*>(tbase + g * TILE_W);
        const ulonglong2* sh2 = reinterpret_cast<const ulonglong2*>(sbase + g * TILE_W);
        ulonglong2 p0 = tr2[0], p1 = tr2[1], p2 = tr2[2], p3 = tr2[3], p4 = tr2[4];
        ulonglong2 q0 = sh2[0], q1 = sh2[1], q2 = sh2[2], q3 = sh2[3], q4 = sh2[4];
        u64 s1 = p0.y, s2 = p1.x, s3 = p1.y, s4 = p2.x,
            s5 = p2.y, s6 = p3.x, s7 = p3.y, s8 = p4.x;
        u64 t0 = q0.x, t1 = q0.y, t2 = q1.x, t3 = q1.y, t4 = q2.x,
            t5 = q2.y, t6 = q3.x, t7 = q3.y, t8 = q4.x;

        // Horizontal folds, all packed add2.
        u64 h0[8], h1[8];
        h0[0] = s4;
        h0[1] = add2(t3, t4);
        h0[2] = add2(s3, s5);
        h0[3] = add2(t2, t5);
        h0[4] = add2(s2, s6);
        h0[5] = add2(t1, t6);
        h0[6] = add2(s1, s7);
        h0[7] = add2(t0, t7);

        h1[0] = s5;
        h1[1] = add2(t4, t5);
        h1[2] = add2(s4, s6);
        h1[3] = add2(t3, t6);
        h1[4] = add2(s3, s7);
        h1[5] = add2(t2, t7);
        h1[6] = add2(s2, s8);
        h1[7] = add2(t1, t8);

        // Weight row wr serves BOTH dy-symmetric output rows:
        //   r1 = g - wr (dy = wr), r2 = g - 14 + wr (dy = 14 - wr).
        #pragma unroll
        for (int wr = 0; wr < 8; ++wr) {
            const int r1 = g - wr;
            const int r2 = g - 14 + wr;
            const bool u1 = (r1 >= 0) && (r1 < 8);
            const bool u2 = (wr < 7) && (r2 >= 0) && (r2 < 8);
            if (u1 || u2) {
                const u64* kw = &sk[wr * 8];
                ulonglong2 w01 = *reinterpret_cast<const ulonglong2*>(kw + 0);
                ulonglong2 w23 = *reinterpret_cast<const ulonglong2*>(kw + 2);
                ulonglong2 w45 = *reinterpret_cast<const ulonglong2*>(kw + 4);
                ulonglong2 w67 = *reinterpret_cast<const ulonglong2*>(kw + 6);
                if (u1) {
                    fma2(acc0[r1], h0[0], w01.x);  fma2(acc1[r1], h1[0], w01.x);
                    fma2(acc0[r1], h0[1], w01.y);  fma2(acc1[r1], h1[1], w01.y);
                    fma2(acc0[r1], h0[2], w23.x);  fma2(acc1[r1], h1[2], w23.x);
                    fma2(acc0[r1], h0[3], w23.y);  fma2(acc1[r1], h1[3], w23.y);
                    fma2(acc0[r1], h0[4], w45.x);  fma2(acc1[r1], h1[4], w45.x);
                    fma2(acc0[r1], h0[5], w45.y);  fma2(acc1[r1], h1[5], w45.y);
                    fma2(acc0[r1], h0[6], w67.x);  fma2(acc1[r1], h1[6], w67.x);
                    fma2(acc0[r1], h0[7], w67.y);  fma2(acc1[r1], h1[7], w67.y);
                }
                if (u2) {
                    fma2(acc0[r2], h0[0], w01.x);  fma2(acc1[r2], h1[0], w01.x);
                    fma2(acc0[r2], h0[1], w01.y);  fma2(acc1[r2], h1[1], w01.y);
                    fma2(acc0[r2], h0[2], w23.x);  fma2(acc1[r2], h1[2], w23.x);
                    fma2(acc0[r2], h0[3], w23.y);  fma2(acc1[r2], h1[3], w23.y);
                    fma2(acc0[r2], h0[4], w45.x);  fma2(acc1[r2], h1[4], w45.x);
                    fma2(acc0[r2], h0[5], w45.y);  fma2(acc1[r2], h1[5], w45.y);
                    fma2(acc0[r2], h0[6], w67.x);  fma2(acc1[r2], h1[6], w67.x);
                    fma2(acc0[r2], h0[7], w67.y);  fma2(acc1[r2], h1[7], w67.y);
                }
            }
        }
    }

    // Fused roll: out[b, y, (x + s) & 1023] = conv[b, y, x].
    #pragma unroll
    for (int r = 0; r < 8; ++r) {
        const int y = y0 + r;
        const int s = shifts[b * IMG_H + y];
        float* orow = out + ((size_t)b * IMG_H + y) * IMG_W;
        float lo0, hi0, lo1, hi1;
        unpack2(acc0[r], lo0, hi0);
        unpack2(acc1[r], lo1, hi1);
        int c0 = (x0 + s) & (IMG_W - 1);
        int c1 = (x0 + 2 + s) & (IMG_W - 1);
        if ((s & 1) == 0) {
            // even shift: c0,c1 even -> aligned float2, never straddle the wrap
            *reinterpret_cast<float2*>(orow + c0) = make_float2(lo0, hi0);
            *reinterpret_cast<float2*>(orow + c1) = make_float2(lo1, hi1);
        } else {
            orow[c0] = lo0;
            orow[(c0 + 1) & (IMG_W - 1)] = hi0;
            orow[c1] = lo1;
            orow[(c1 + 1) & (IMG_W - 1)] = hi1;
        }
    }
}

extern "C" void kernel_launch(void* const* d_in, const int* in_sizes, int n_in,
                              void* d_out, int out_size) {
    const float* img = nullptr;
    const float* kern = nullptr;
    const int*   shifts = nullptr;
    for (int i = 0; i < n_in; ++i) {
        if (in_sizes[i] == NB * IMG_H * IMG_W)      img    = (const float*)d_in[i];
        else if (in_sizes[i] == KS * KS)            kern   = (const float*)d_in[i];
        else if (in_sizes[i] == NB * IMG_H)         shifts = (const int*)d_in[i];
    }
    cudaFuncSetAttribute(stem_conv_roll,
                         cudaFuncAttributeMaxDynamicSharedMemorySize, SMEM_BYTES);
    dim3 grid(IMG_W / 256, IMG_H / 32, NB);
    stem_conv_roll<<<grid, 256, SMEM_BYTES>>>(img, kern, shifts, (float*)d_out);
}

// round 16
// speedup vs baseline: 1.1530x; 1.1523x over previous
#include <cuda_runtime.h>
#include <cuda_bf16.h>

#define IMG_W 1024
#define IMG_H 1024
#define KS 15
#define NB 32

// Input tile staged in smem: x covers [bx*256-8, bx*256+264) = 272 floats,
// y covers [by*32-7, by*32+39) = 46 rows. Zero-padded outside the image.
#define TILE_W 272
#define TILE_HH 46
#define SMEM_BYTES (TILE_W * TILE_HH * 4)

typedef unsigned long long u64;

// Folded weights in CONSTANT memory: c_w2[wr*4 + j] = ((w_{2j},w_{2j}),(w_{2j+1},w_{2j+1}))
// with w_e = k[wr][7+e]. Warp-uniform, compile-time-indexed -> uniform/const
// datapath (LDCU/ULDC), off the LSU pipe entirely.
__constant__ __align__(16) ulonglong2 c_w2[32];
__device__   __align__(16) u64 g_wtmp[64];

// ---- packed fp32x2 helpers (Blackwell, PTX-only) ----
__device__ __forceinline__ u64 pack2(float lo, float hi) {
    u64 r;
    asm("mov.b64 %0, {%1, %2};" : "=l"(r) : "f"(lo), "f"(hi));
    return r;
}
__device__ __forceinline__ void unpack2(u64 v, float& lo, float& hi) {
    asm("mov.b64 {%0, %1}, %2;" : "=f"(lo), "=f"(hi) : "l"(v));
}
__device__ __forceinline__ void fma2(u64& d, u64 a, u64 b) {
    asm("fma.rn.f32x2 %0, %1, %2, %3;" : "=l"(d) : "l"(a), "l"(b), "l"(d));
}
__device__ __forceinline__ u64 add2(u64 a, u64 b) {
    u64 r;
    asm("add.rn.f32x2 %0, %1, %2;" : "=l"(r) : "l"(a), "l"(b));
    return r;
}
// (hi(a), lo(b)) — odd-offset pair from two aligned pairs
__device__ __forceinline__ u64 mk_t(u64 a, u64 b) {
    float alo, ahi, blo, bhi;
    unpack2(a, alo, ahi);
    unpack2(b, blo, bhi);
    return pack2(ahi, blo);
}
__device__ __forceinline__ unsigned smem_u32(const void* p) {
    unsigned r;
    asm("{ .reg .u64 t; cvta.to.shared.u64 t, %1; cvt.u32.u64 %0, t; }" : "=r"(r) : "l"(p));
    return r;
}

// Prep: fold the 15x15 Airy kernel (dx+dy symmetric) into 8 rows x 8 (w,w) pairs.
__global__ void fold_weights(const float* __restrict__ kern) {
    int t = threadIdx.x;          // 0..63
    int wr = t >> 3, e = t & 7;
    float w = kern[wr * KS + 7 + e];
    g_wtmp[t] = pack2(w, w);
}

// Thread: 4 px (two f32x2 pairs) x 8 output rows. Block 256 thr = 8 warps:
// 2 in x, 4 in y. Block tile: 256 px * 32 rows. Grid (4, 32, 32).
// Each constant weight fetch serves BOTH dy-symmetric output rows.
__global__ __launch_bounds__(256, 2) void stem_conv_roll(
    const float* __restrict__ in,
    const int* __restrict__ shifts, float* __restrict__ out)
{
    extern __shared__ char dynsmem[];
    float* sIn = reinterpret_cast<float*>(dynsmem);   // [TILE_HH][TILE_W]

    const int tid = threadIdx.x;
    const int b   = blockIdx.z;
    const float* img = in + (size_t)b * (IMG_H * IMG_W);

    // ---- Stage input tile via cp.async, zero-filled outside the image.
    // Every partially-OOB float4 in this geometry is fully OOB, so
    // src_size=0 zfill handles all padding.
    {
        const int gxb = blockIdx.x * 256 - 8;
        const int gyb = blockIdx.y * 32 - 7;
        const unsigned sbase = smem_u32(dynsmem);
        for (int idx = tid; idx < TILE_HH * (TILE_W / 4); idx += 256) {
            const int ry  = idx / (TILE_W / 4);
            const int rx4 = idx - ry * (TILE_W / 4);
            const int gy  = gyb + ry;
            const int gx  = gxb + rx4 * 4;
            const bool ok = (gy >= 0) && (gy < IMG_H) && (gx >= 0) && (gx <= IMG_W - 4);
            const float* src = ok ? (img + (size_t)gy * IMG_W + gx) : img;
            const unsigned dst = sbase + (unsigned)(ry * TILE_W + rx4 * 4) * 4u;
            const int sz = ok ? 16 : 0;
            asm volatile("cp.async.ca.shared.global [%0], [%1], 16, %2;"
                         :: "r"(dst), "l"(src), "r"(sz));
        }
    }
    asm volatile("cp.async.commit_group;\n\tcp.async.wait_group 0;" ::: "memory");
    __syncthreads();

    const int lane = tid & 31;
    const int warp = tid >> 5;
    const int wx = warp & 1;
    const int wy = warp >> 1;
    const int xl = wx * 128 + lane * 4;       // local x of first px (mult of 4)
    const int x0 = blockIdx.x * 256 + xl;
    const int y0 = blockIdx.y * 32 + wy * 8;

    u64 acc0[8], acc1[8];
    #pragma unroll
    for (int r = 0; r < 8; ++r) { acc0[r] = 0ull; acc1[r] = 0ull; }

    const float* tbase = sIn + wy * 8 * TILE_W + xl;

    #pragma unroll
    for (int g = 0; g < 22; ++g) {
        const ulonglong2* tr2 = reinterpret_cast<const ulonglong2*>(tbase + g * TILE_W);
        ulonglong2 p0 = tr2[0], p1 = tr2[1], p2 = tr2[2], p3 = tr2[3], p4 = tr2[4];
        u64 s0 = p0.x, s1 = p0.y, s2 = p1.x, s3 = p1.y, s4 = p2.x,
            s5 = p2.y, s6 = p3.x, s7 = p3.y, s8 = p4.x, s9 = p4.y;
        // Odd-offset pairs t_j = (ga[2j+1], ga[2j+2]), shared by h0 and h1.
        u64 t0 = mk_t(s0, s1), t1 = mk_t(s1, s2), t2 = mk_t(s2, s3),
            t3 = mk_t(s3, s4), t4 = mk_t(s4, s5), t5 = mk_t(s5, s6),
            t6 = mk_t(s6, s7), t7 = mk_t(s7, s8), t8 = mk_t(s8, s9);

        // Horizontal folds, all packed add2.
        u64 h0[8], h1[8];
        h0[0] = s4;
        h0[1] = add2(t3, t4);
        h0[2] = add2(s3, s5);
        h0[3] = add2(t2, t5);
        h0[4] = add2(s2, s6);
        h0[5] = add2(t1, t6);
        h0[6] = add2(s1, s7);
        h0[7] = add2(t0, t7);

        h1[0] = s5;
        h1[1] = add2(t4, t5);
        h1[2] = add2(s4, s6);
        h1[3] = add2(t3, t6);
        h1[4] = add2(s3, s7);
        h1[5] = add2(t2, t7);
        h1[6] = add2(s2, s8);
        h1[7] = add2(t1, t8);

        // Weight row wr serves BOTH dy-symmetric output rows:
        //   r1 = g - wr (dy = wr), r2 = g - 14 + wr (dy = 14 - wr).
        // Weights come from CONSTANT memory with compile-time indices.
        #pragma unroll
        for (int wr = 0; wr < 8; ++wr) {
            const int r1 = g - wr;
            const int r2 = g - 14 + wr;
            const bool u1 = (r1 >= 0) && (r1 < 8);
            const bool u2 = (wr < 7) && (r2 >= 0) && (r2 < 8);
            if (u1 || u2) {
                ulonglong2 w01 = c_w2[wr * 4 + 0];
                ulonglong2 w23 = c_w2[wr * 4 + 1];
                ulonglong2 w45 = c_w2[wr * 4 + 2];
                ulonglong2 w67 = c_w2[wr * 4 + 3];
                if (u1) {
                    fma2(acc0[r1], h0[0], w01.x);  fma2(acc1[r1], h1[0], w01.x);
                    fma2(acc0[r1], h0[1], w01.y);  fma2(acc1[r1], h1[1], w01.y);
                    fma2(acc0[r1], h0[2], w23.x);  fma2(acc1[r1], h1[2], w23.x);
                    fma2(acc0[r1], h0[3], w23.y);  fma2(acc1[r1], h1[3], w23.y);
                    fma2(acc0[r1], h0[4], w45.x);  fma2(acc1[r1], h1[4], w45.x);
                    fma2(acc0[r1], h0[5], w45.y);  fma2(acc1[r1], h1[5], w45.y);
                    fma2(acc0[r1], h0[6], w67.x);  fma2(acc1[r1], h1[6], w67.x);
                    fma2(acc0[r1], h0[7], w67.y);  fma2(acc1[r1], h1[7], w67.y);
                }
                if (u2) {
                    fma2(acc0[r2], h0[0], w01.x);  fma2(acc1[r2], h1[0], w01.x);
                    fma2(acc0[r2], h0[1], w01.y);  fma2(acc1[r2], h1[1], w01.y);
                    fma2(acc0[r2], h0[2], w23.x);  fma2(acc1[r2], h1[2], w23.x);
                    fma2(acc0[r2], h0[3], w23.y);  fma2(acc1[r2], h1[3], w23.y);
                    fma2(acc0[r2], h0[4], w45.x);  fma2(acc1[r2], h1[4], w45.x);
                    fma2(acc0[r2], h0[5], w45.y);  fma2(acc1[r2], h1[5], w45.y);
                    fma2(acc0[r2], h0[6], w67.x);  fma2(acc1[r2], h1[6], w67.x);
                    fma2(acc0[r2], h0[7], w67.y);  fma2(acc1[r2], h1[7], w67.y);
                }
            }
        }
    }

    // Fused roll: out[b, y, (x + s) & 1023] = conv[b, y, x].
    #pragma unroll
    for (int r = 0; r < 8; ++r) {
        const int y = y0 + r;
        const int s = shifts[b * IMG_H + y];
        float* orow = out + ((size_t)b * IMG_H + y) * IMG_W;
        float lo0, hi0, lo1, hi1;
        unpack2(acc0[r], lo0, hi0);
        unpack2(acc1[r], lo1, hi1);
        int c0 = (x0 + s) & (IMG_W - 1);
        int c1 = (x0 + 2 + s) & (IMG_W - 1);
        if ((s & 1) == 0) {
            // even shift: c0,c1 even -> aligned float2, never straddle the wrap
            *reinterpret_cast<float2*>(orow + c0) = make_float2(lo0, hi0);
            *reinterpret_cast<float2*>(orow + c1) = make_float2(lo1, hi1);
        } else {
            orow[c0] = lo0;
            orow[(c0 + 1) & (IMG_W - 1)] = hi0;
            orow[c1] = lo1;
            orow[(c1 + 1) & (IMG_W - 1)] = hi1;
        }
    }
}

extern "C" void kernel_launch(void* const* d_in, const int* in_sizes, int n_in,
                              void* d_out, int out_size) {
    const float* img = nullptr;
    const float* kern = nullptr;
    const int*   shifts = nullptr;
    for (int i = 0; i < n_in; ++i) {
        if (in_sizes[i] == NB * IMG_H * IMG_W)      img    = (const float*)d_in[i];
        else if (in_sizes[i] == KS * KS)            kern   = (const float*)d_in[i];
        else if (in_sizes[i] == NB * IMG_H)         shifts = (const int*)d_in[i];
    }

    // 1) Fold weights into __device__ scratch.
    fold_weights<<<1, 64>>>(kern);
    // 2) D2D copy into __constant__ bank (graph-capturable memcpy node).
    void* src = nullptr;
    cudaGetSymbolAddress(&src, g_wtmp);
    cudaMemcpyToSymbolAsync(c_w2, src, 64 * sizeof(u64), 0,
                            cudaMemcpyDeviceToDevice, 0);
    // 3) Main kernel.
    cudaFuncSetAttribute(stem_conv_roll,
                         cudaFuncAttributeMaxDynamicSharedMemorySize, SMEM_BYTES);
    dim3 grid(IMG_W / 256, IMG_H / 32, NB);
    stem_conv_roll<<<grid, 256, SMEM_BYTES>>>(img, shifts, (float*)d_out);
}

// round 17
// speedup vs baseline: 1.2936x; 1.1220x over previous
#include <cuda_runtime.h>
#include <cuda_bf16.h>

#define IMG_W 1024
#define IMG_H 1024
#define KS 15
#define NB 32

// Input tile staged in smem: x covers [bx*256-8, bx*256+264) = 272 floats,
// y covers [by*32-7, by*32+39) = 46 rows. Zero-padded outside the image.
#define TILE_W 272
#define TILE_HH 46
#define SMEM_BYTES (TILE_W * TILE_HH * 4)

typedef unsigned long long u64;

// Folded weights in CONSTANT memory: c_w2[wr*4 + j] = ((w_{2j},w_{2j}),(w_{2j+1},w_{2j+1}))
// with w_e = k[wr][7+e].
__constant__ __align__(16) ulonglong2 c_w2[32];
__device__   __align__(16) u64 g_wtmp[64];

// ---- packed fp32x2 helpers (Blackwell, PTX-only) ----
__device__ __forceinline__ u64 pack2(float lo, float hi) {
    u64 r;
    asm("mov.b64 %0, {%1, %2};" : "=l"(r) : "f"(lo), "f"(hi));
    return r;
}
__device__ __forceinline__ void unpack2(u64 v, float& lo, float& hi) {
    asm("mov.b64 {%0, %1}, %2;" : "=f"(lo), "=f"(hi) : "l"(v));
}
__device__ __forceinline__ void fma2(u64& d, u64 a, u64 b) {
    asm("fma.rn.f32x2 %0, %1, %2, %3;" : "=l"(d) : "l"(a), "l"(b), "l"(d));
}
__device__ __forceinline__ u64 add2(u64 a, u64 b) {
    u64 r;
    asm("add.rn.f32x2 %0, %1, %2;" : "=l"(r) : "l"(a), "l"(b));
    return r;
}
// Odd-e fold: two scalar FADDs whose results form one aligned pair.
// Operands are halves of already-live pair registers; the mov extraction and
// pack are register-allocator-elidable (no pair-shuffle data movement).
__device__ __forceinline__ u64 fold_sc(float a, float b, float c, float d) {
    return pack2(a + b, c + d);
}
__device__ __forceinline__ unsigned smem_u32(const void* p) {
    unsigned r;
    asm("{ .reg .u64 t; cvta.to.shared.u64 t, %1; cvt.u32.u64 %0, t; }" : "=r"(r) : "l"(p));
    return r;
}

// Prep: fold the 15x15 Airy kernel (dx+dy symmetric) into 8 rows x 8 (w,w) pairs.
__global__ void fold_weights(const float* __restrict__ kern) {
    int t = threadIdx.x;          // 0..63
    int wr = t >> 3, e = t & 7;
    float w = kern[wr * KS + 7 + e];
    g_wtmp[t] = pack2(w, w);
}

// Thread: 4 px (two f32x2 pairs) x 8 output rows. Block 256 thr = 8 warps:
// 2 in x, 4 in y. Block tile: 256 px * 32 rows. Grid (4, 32, 32).
// Each constant weight fetch serves BOTH dy-symmetric output rows.
__global__ __launch_bounds__(256, 2) void stem_conv_roll(
    const float* __restrict__ in,
    const int* __restrict__ shifts, float* __restrict__ out)
{
    extern __shared__ char dynsmem[];
    float* sIn = reinterpret_cast<float*>(dynsmem);   // [TILE_HH][TILE_W]

    const int tid = threadIdx.x;
    const int b   = blockIdx.z;
    const float* img = in + (size_t)b * (IMG_H * IMG_W);

    // ---- Stage input tile via cp.async, zero-filled outside the image.
    {
        const int gxb = blockIdx.x * 256 - 8;
        const int gyb = blockIdx.y * 32 - 7;
        const unsigned sbase = smem_u32(dynsmem);
        for (int idx = tid; idx < TILE_HH * (TILE_W / 4); idx += 256) {
            const int ry  = idx / (TILE_W / 4);
            const int rx4 = idx - ry * (TILE_W / 4);
            const int gy  = gyb + ry;
            const int gx  = gxb + rx4 * 4;
            const bool ok = (gy >= 0) && (gy < IMG_H) && (gx >= 0) && (gx <= IMG_W - 4);
            const float* src = ok ? (img + (size_t)gy * IMG_W + gx) : img;
            const unsigned dst = sbase + (unsigned)(ry * TILE_W + rx4 * 4) * 4u;
            const int sz = ok ? 16 : 0;
            asm volatile("cp.async.ca.shared.global [%0], [%1], 16, %2;"
                         :: "r"(dst), "l"(src), "r"(sz));
        }
    }
    asm volatile("cp.async.commit_group;\n\tcp.async.wait_group 0;" ::: "memory");
    __syncthreads();

    const int lane = tid & 31;
    const int warp = tid >> 5;
    const int wx = warp & 1;
    const int wy = warp >> 1;
    const int xl = wx * 128 + lane * 4;       // local x of first px (mult of 4)
    const int x0 = blockIdx.x * 256 + xl;
    const int y0 = blockIdx.y * 32 + wy * 8;

    u64 acc0[8], acc1[8];
    #pragma unroll
    for (int r = 0; r < 8; ++r) { acc0[r] = 0ull; acc1[r] = 0ull; }

    const float* tbase = sIn + wy * 8 * TILE_W + xl;

    #pragma unroll
    for (int g = 0; g < 22; ++g) {
        const ulonglong2* tr2 = reinterpret_cast<const ulonglong2*>(tbase + g * TILE_W);
        ulonglong2 p0 = tr2[0], p1 = tr2[1], p2 = tr2[2], p3 = tr2[3], p4 = tr2[4];
        // Aligned pairs: sA=(ga0,ga1) sB=(ga2,ga3) ... sJ=(ga18,ga19)
        u64 sA = p0.x, sB = p0.y, sC = p1.x, sD = p1.y, sE = p2.x,
            sF = p2.y, sG = p3.x, sH = p3.y, sI = p4.x, sJ = p4.y;
        // Scalar views (halves of live pair registers; extraction elided).
        float ga0, ga1, ga2, ga3, ga4, ga5, ga6, ga7, ga8, ga9,
              ga10, ga11, ga12, ga13, ga14, ga15, ga16, ga17, ga18, ga19;
        unpack2(sA, ga0,  ga1);   unpack2(sB, ga2,  ga3);
        unpack2(sC, ga4,  ga5);   unpack2(sD, ga6,  ga7);
        unpack2(sE, ga8,  ga9);   unpack2(sF, ga10, ga11);
        unpack2(sG, ga12, ga13);  unpack2(sH, ga14, ga15);
        unpack2(sI, ga16, ga17);  unpack2(sJ, ga18, ga19);

        // Horizontal folds. Even e: add2 on existing aligned pairs.
        // Odd e: two scalar FADDs forming a fresh aligned pair (no shuffles).
        u64 h0[8], h1[8];
        h0[0] = sE;
        h0[1] = fold_sc(ga7, ga9,  ga8, ga10);
        h0[2] = add2(sD, sF);
        h0[3] = fold_sc(ga5, ga11, ga6, ga12);
        h0[4] = add2(sC, sG);
        h0[5] = fold_sc(ga3, ga13, ga4, ga14);
        h0[6] = add2(sB, sH);
        h0[7] = fold_sc(ga1, ga15, ga2, ga16);

        h1[0] = sF;
        h1[1] = fold_sc(ga9, ga11, ga10, ga12);
        h1[2] = add2(sE, sG);
        h1[3] = fold_sc(ga7, ga13, ga8, ga14);
        h1[4] = add2(sD, sH);
        h1[5] = fold_sc(ga5, ga15, ga6, ga16);
        h1[6] = add2(sC, sI);
        h1[7] = fold_sc(ga3, ga17, ga4, ga18);

        // Weight row wr serves BOTH dy-symmetric output rows:
        //   r1 = g - wr (dy = wr), r2 = g - 14 + wr (dy = 14 - wr).
        #pragma unroll
        for (int wr = 0; wr < 8; ++wr) {
            const int r1 = g - wr;
            const int r2 = g - 14 + wr;
            const bool u1 = (r1 >= 0) && (r1 < 8);
            const bool u2 = (wr < 7) && (r2 >= 0) && (r2 < 8);
            if (u1 || u2) {
                ulonglong2 w01 = c_w2[wr * 4 + 0];
                ulonglong2 w23 = c_w2[wr * 4 + 1];
                ulonglong2 w45 = c_w2[wr * 4 + 2];
                ulonglong2 w67 = c_w2[wr * 4 + 3];
                if (u1) {
                    fma2(acc0[r1], h0[0], w01.x);  fma2(acc1[r1], h1[0], w01.x);
                    fma2(acc0[r1], h0[1], w01.y);  fma2(acc1[r1], h1[1], w01.y);
                    fma2(acc0[r1], h0[2], w23.x);  fma2(acc1[r1], h1[2], w23.x);
                    fma2(acc0[r1], h0[3], w23.y);  fma2(acc1[r1], h1[3], w23.y);
                    fma2(acc0[r1], h0[4], w45.x);  fma2(acc1[r1], h1[4], w45.x);
                    fma2(acc0[r1], h0[5], w45.y);  fma2(acc1[r1], h1[5], w45.y);
                    fma2(acc0[r1], h0[6], w67.x);  fma2(acc1[r1], h1[6], w67.x);
                    fma2(acc0[r1], h0[7], w67.y);  fma2(acc1[r1], h1[7], w67.y);
                }
                if (u2) {
                    fma2(acc0[r2], h0[0], w01.x);  fma2(acc1[r2], h1[0], w01.x);
                    fma2(acc0[r2], h0[1], w01.y);  fma2(acc1[r2], h1[1], w01.y);
                    fma2(acc0[r2], h0[2], w23.x);  fma2(acc1[r2], h1[2], w23.x);
                    fma2(acc0[r2], h0[3], w23.y);  fma2(acc1[r2], h1[3], w23.y);
                    fma2(acc0[r2], h0[4], w45.x);  fma2(acc1[r2], h1[4], w45.x);
                    fma2(acc0[r2], h0[5], w45.y);  fma2(acc1[r2], h1[5], w45.y);
                    fma2(acc0[r2], h0[6], w67.x);  fma2(acc1[r2], h1[6], w67.x);
                    fma2(acc0[r2], h0[7], w67.y);  fma2(acc1[r2], h1[7], w67.y);
                }
            }
        }
    }

    // Fused roll: out[b, y, (x + s) & 1023] = conv[b, y, x].
    #pragma unroll
    for (int r = 0; r < 8; ++r) {
        const int y = y0 + r;
        const int s = shifts[b * IMG_H + y];
        float* orow = out + ((size_t)b * IMG_H + y) * IMG_W;
        float lo0, hi0, lo1, hi1;
        unpack2(acc0[r], lo0, hi0);
        unpack2(acc1[r], lo1, hi1);
        int c0 = (x0 + s) & (IMG_W - 1);
        int c1 = (x0 + 2 + s) & (IMG_W - 1);
        if ((s & 1) == 0) {
            // even shift: c0,c1 even -> aligned float2, never straddle the wrap
            *reinterpret_cast<float2*>(orow + c0) = make_float2(lo0, hi0);
            *reinterpret_cast<float2*>(orow + c1) = make_float2(lo1, hi1);
        } else {
            orow[c0] = lo0;
            orow[(c0 + 1) & (IMG_W - 1)] = hi0;
            orow[c1] = lo1;
            orow[(c1 + 1) & (IMG_W - 1)] = hi1;
        }
    }
}

extern "C" void kernel_launch(void* const* d_in, const int* in_sizes, int n_in,
                              void* d_out, int out_size) {
    const float* img = nullptr;
    const float* kern = nullptr;
    const int*   shifts = nullptr;
    for (int i = 0; i < n_in; ++i) {
        if (in_sizes[i] == NB * IMG_H * IMG_W)      img    = (const float*)d_in[i];
        else if (in_sizes[i] == KS * KS)            kern   = (const float*)d_in[i];
        else if (in_sizes[i] == NB * IMG_H)         shifts = (const int*)d_in[i];
    }

    // 1) Fold weights into __device__ scratch.
    fold_weights<<<1, 64>>>(kern);
    // 2) D2D copy into __constant__ bank (graph-capturable memcpy node).
    void* src = nullptr;
    cudaGetSymbolAddress(&src, g_wtmp);
    cudaMemcpyToSymbolAsync(c_w2, src, 64 * sizeof(u64), 0,
                            cudaMemcpyDeviceToDevice, 0);
    // 3) Main kernel.
    cudaFuncSetAttribute(stem_conv_roll,
                         cudaFuncAttributeMaxDynamicSharedMemorySize, SMEM_BYTES);
    dim3 grid(IMG_W / 256, IMG_H / 32, NB);
    stem_conv_roll<<<grid, 256, SMEM_BYTES>>>(img, shifts, (float*)d_out);
}